// round 8
// baseline (speedup 1.0000x reference)
#include <cuda_runtime.h>
#include <cuda_bf16.h>
#include <cstdint>

#define BB   64
#define CIN  12
#define LL   4096
#define TT   20
#define NC1  64
#define NC2  64
#define NCLS 4
#define NLT  128                 // l positions per tile
#define NTILES (LL / NLT)        // 32
#define NBP  132                 // padded B rows (130 used)

typedef unsigned long long ull;
typedef unsigned int u32;

// spike bits: 2x u32 per (b,t,l)
__device__ u32 g_s1[BB * TT * LL * 2];
// per (b,c2) spike counts
__device__ float g_pool[BB * NC2];
// int8 A fragments, 3 fixed-point planes, exact mma lane order:
// [(((j*3+kk)*2+s)*3+p)*128 + lane*4 + r]
__device__ u32 g_Aq[4 * 3 * 2 * 3 * 128];   // 9216 u32

// ---------------- packed f32x2 helpers (conv1) ------------------------------
#define FMA_F32X2(d, a, b, c) \
    asm("fma.rn.f32x2 %0, %1, %2, %3;" : "=l"(d) : "l"(a), "l"(b), "l"(c))
#define PACK_F32X2(out, lo, hi) \
    asm("mov.b64 %0, {%1, %2};" : "=l"(out) : "f"(lo), "f"(hi))
#define UNPACK_F32X2(lo, hi, in) \
    asm("mov.b64 {%0, %1}, %2;" : "=f"(lo), "=f"(hi) : "l"(in))

// mma.sync m16n8k32 s8 x s8 -> s32 (baseline PTX, sm_75+)
#define MMA_S8(d, a, b) \
    asm volatile("mma.sync.aligned.m16n8k32.row.col.s32.s8.s8.s32 " \
        "{%0,%1,%2,%3}, {%4,%5,%6,%7}, {%8,%9}, {%0,%1,%2,%3};" \
        : "+r"((d)[0]), "+r"((d)[1]), "+r"((d)[2]), "+r"((d)[3]) \
        : "r"((a).x), "r"((a).y), "r"((a).z), "r"((a).w), \
          "r"((b).x), "r"((b).y))

// channel permutation (baked into A) matching the shift/AND byte-spread decode:
// B u32 index jj, byte e holds klocal = 16*(jj&1) + 4*(jj>>1) + e, and decode
// puts mask-bit (jj + 8e) there -> c1(kappa) below.
__device__ __forceinline__ int chan_for_k(int kappa) {
    int s  = kappa >> 5;
    int kl = kappa & 31;
    return 32 * s + ((kl >> 4) & 1) + 2 * ((kl >> 2) & 3) + 8 * (kl & 3);
}

// ---------------------------------------------------------------------------
// k_pre: zero pool + build int8 A planes.
// w = p0*2^-7 + p1*2^-14 + p2*2^-21 + eps, |eps| <= 2^-22.
// Digit ranges: |p0|<=127 (no clamp hit: |w|<0.5), |p1|<=64, |p2|<=64 — all
// provably fit int8 (7-bit digit spacing).
// ---------------------------------------------------------------------------
__global__ void k_pre(const float* __restrict__ w2) {
    int i = blockIdx.x * blockDim.x + threadIdx.x;
    if (i < BB * NC2) g_pool[i] = 0.0f;
    if (i < 9216) {
        int r     = i & 3;
        int idx4  = i >> 2;
        int lane  = idx4 & 31;
        int rest  = idx4 >> 5;        // ((j*3+kk)*2+s)*3 + p
        int p     = rest % 3;
        int rest2 = rest / 3;
        int s     = rest2 & 1;
        int kkj   = rest2 >> 1;
        int kk    = kkj % 3;
        int j     = kkj / 3;
        int gid   = lane >> 2;
        int t4    = lane & 3;
        int m     = 16 * j + gid + 8 * (r & 1);
        u32 outw = 0;
#pragma unroll
        for (int e = 0; e < 4; e++) {
            int kl = 4 * t4 + e + 16 * (r >> 1);
            int c1 = chan_for_k(32 * s + kl);
            float wv = w2[m * (NC1 * 3) + c1 * 3 + kk];
            float p0 = rintf(wv * 128.0f);
            p0 = fminf(fmaxf(p0, -127.0f), 127.0f);
            float r1 = wv - p0 * 0.0078125f;             // |r1| <= 2^-8
            float p1 = rintf(r1 * 16384.0f);             // |p1| <= 64
            float r2 = r1 - p1 * (1.0f / 16384.0f);      // |r2| <= 2^-15
            float p2 = rintf(r2 * 2097152.0f);           // |p2| <= 64
            float sel = (p == 0) ? p0 : (p == 1) ? p1 : p2;
            int q = (int)sel;
            outw |= ((u32)(q & 0xFF)) << (8 * e);
        }
        g_Aq[i] = outw;
    }
}

// ---------------------------------------------------------------------------
// k_conv1: conv1 + threshold -> bit-packed spikes (TAU1=1 => stateless).
// (unchanged: packed f32x2 over contiguous t axis)
// ---------------------------------------------------------------------------
__global__ __launch_bounds__(256) void k_conv1(
        const float* __restrict__ x,
        const float* __restrict__ w1,
        const float* __restrict__ b1,
        const float* __restrict__ pgain,
        const float* __restrict__ pth1) {
    __shared__ __align__(16) float s_x[CIN][34][TT];

    const int l0  = blockIdx.x * 32;
    const int b   = blockIdx.y;
    const int tid = threadIdx.x;

    for (int i = tid; i < CIN * 34 * TT; i += 256) {
        int c   = i / (34 * TT);
        int rem = i % (34 * TT);
        int lx  = rem / TT;
        int t   = rem % TT;
        int gl  = l0 - 1 + lx;
        float v = 0.0f;
        if (gl >= 0 && gl < LL)
            v = x[((size_t)(b * CIN + c) * LL + gl) * TT + t];
        s_x[c][lx][t] = v;
    }

    const int w    = tid >> 5;
    const int lane = tid & 31;
    const int half = w & 1;
    const int pair = w >> 1;
    const int c1   = half * 32 + lane;

    ull wrp[CIN][3];
#pragma unroll
    for (int c = 0; c < CIN; c++)
#pragma unroll
        for (int k = 0; k < 3; k++) {
            float wv = w1[c1 * (CIN * 3) + c * 3 + k];
            PACK_F32X2(wrp[c][k], wv, wv);
        }
    const float bias = b1[c1];
    const float gain = *pgain;
    const float th1  = *pth1;

    __syncthreads();

    for (int task = pair; task < 160; task += 4) {
        int ll = task & 31;
        int tg = task >> 5;
        int t0 = tg * 4;
        ull a01 = 0ull, a23 = 0ull;
#pragma unroll
        for (int c = 0; c < CIN; c++) {
#pragma unroll
            for (int k = 0; k < 3; k++) {
                ulonglong2 xq = *(const ulonglong2*)&s_x[c][ll + k][t0];
                FMA_F32X2(a01, xq.x, wrp[c][k], a01);
                FMA_F32X2(a23, xq.y, wrp[c][k], a23);
            }
        }
        float a[4];
        UNPACK_F32X2(a[0], a[1], a01);
        UNPACK_F32X2(a[2], a[3], a23);
        int gl = l0 + ll;
#pragma unroll
        for (int j = 0; j < 4; j++) {
            float i1 = (a[j] + bias) * gain;
            unsigned m = __ballot_sync(0xffffffffu, i1 >= th1);
            if (lane == 0)
                g_s1[((size_t)(b * TT + (t0 + j)) * LL + gl) * 2 + half] = m;
        }
    }
}

// ---------------------------------------------------------------------------
// k_snn: conv2 via int8 mma.sync (3 exact fixed-point planes) + LIF.
// CTA = (b, 128-l tile), 512 threads = 16 warps; warp = m-tile j x n-quarter q.
// Per t: byte-spread decode -> int8 B [2 ksteps x 130n x 32k], double-buffered;
// exact recombine via two <2^24 float converts -> LIF in registers.
// ---------------------------------------------------------------------------
#define SNN_SMEM ((9216 + 2 * 2112) * 4)     // 53760 bytes

__global__ __launch_bounds__(512, 1) void k_snn(
        const float* __restrict__ b2,
        const float* __restrict__ pgain,
        const float* __restrict__ pth2) {
    extern __shared__ __align__(16) u32 smw[];
    u32* Ash = smw;                 // 9216 u32
    u32* Bs  = smw + 9216;          // 2 x 2112 u32

    const int tid = threadIdx.x;
    const int b   = blockIdx.x >> 5;
    const int l0  = (blockIdx.x & 31) * NLT;

    // stage A fragments (L2-hot, identical for every CTA)
    for (int i = tid; i < 2304; i += 512)
        ((uint4*)Ash)[i] = ((const uint4*)g_Aq)[i];

    const int w    = tid >> 5;
    const int lane = tid & 31;
    const int j    = w & 3;       // m-tile (16 c2 rows)
    const int q    = w >> 2;      // n-quarter (32 l)
    const int gid  = lane >> 2;
    const int tid4 = lane & 3;

    const float gain   = *pgain;
    const float th2    = *pth2;
    const float invtau = 1.0f / 0.9f;
    const float bg0    = b2[16 * j + gid] * gain;
    const float bg1    = b2[16 * j + gid + 8] * gain;

    // decode task assignment (260 tasks over 512 threads)
    const bool dact = tid < 260;
    int dh = 0, dn = 0;
    bool inrange = false;
    size_t gstep = 0, gaddr = 0;
    if (dact) {
        dh = (tid >= 130) ? 1 : 0;
        dn = tid - 130 * dh;
        int gl  = l0 - 1 + dn;
        inrange = (gl >= 0 && gl < LL);
        if (inrange) {
            gaddr = ((size_t)(b * TT) * LL + gl) * 2 + dh;
            gstep = (size_t)LL * 2;
        }
    }

    float v2[16], cnt[16];
#pragma unroll
    for (int i = 0; i < 16; i++) { v2[i] = 0.0f; cnt[i] = 0.0f; }

    u32 m_next = 0;
    if (dact && inrange) m_next = g_s1[gaddr];

    __syncthreads();

    for (int t = 0; t < TT; t++) {
        const int p = t & 1;
        u32* Bp = Bs + p * 2112;

        // ---- decode spikes for t (byte-spread); prefetch t+1 ----
        u32 mcur = m_next;
        if (dact && inrange && t + 1 < TT)
            m_next = g_s1[gaddr + (size_t)(t + 1) * gstep];
        if (dact) {
            u32 o[8];
#pragma unroll
            for (int jj = 0; jj < 8; jj++)
                o[jj] = (mcur >> jj) & 0x01010101u;
            u32* rr = Bp + ((dh * NBP) + dn) * 8;
            ((uint4*)rr)[0] = make_uint4(o[0], o[1], o[2], o[3]);
            ((uint4*)rr)[1] = make_uint4(o[4], o[5], o[6], o[7]);
        }
        __syncthreads();

        // ---- IMMA: 2 ksteps x 3 taps x 3 planes x 4 n-tiles (nt halves) ----
#pragma unroll
        for (int nh = 0; nh < 2; nh++) {
            int acc[3][2][4];
#pragma unroll
            for (int pl = 0; pl < 3; pl++)
#pragma unroll
                for (int n2 = 0; n2 < 2; n2++)
#pragma unroll
                    for (int r = 0; r < 4; r++) acc[pl][n2][r] = 0;

#pragma unroll
            for (int s = 0; s < 2; s++) {
#pragma unroll
                for (int kk = 0; kk < 3; kk++) {
                    int abase = (((j * 3 + kk) * 2 + s) * 3) * 128 + lane * 4;
                    uint4 a0 = *(const uint4*)&Ash[abase];
                    uint4 a1 = *(const uint4*)&Ash[abase + 128];
                    uint4 a2 = *(const uint4*)&Ash[abase + 256];
#pragma unroll
                    for (int n2 = 0; n2 < 2; n2++) {
                        int nrow = q * 32 + (nh * 2 + n2) * 8 + gid + kk;
                        uint2 bb = *(const uint2*)&Bp[(s * NBP + nrow) * 8 + tid4 * 2];
                        MMA_S8(acc[0][n2], a0, bb);
                        MMA_S8(acc[1][n2], a1, bb);
                        MMA_S8(acc[2][n2], a2, bb);
                    }
                }
            }

            // ---- exact recombine + LIF (registers) ----
#pragma unroll
            for (int n2 = 0; n2 < 2; n2++)
#pragma unroll
                for (int r = 0; r < 4; r++) {
                    int a0i  = acc[0][n2][r];                       // |.| <= 24384  (exact in f32)
                    int lowc = (acc[1][n2][r] << 7) + acc[2][n2][r]; // |.| <= 1.6M  (exact in f32)
                    float f  = fmaf((float)lowc, 4.76837158203125e-7f,   // 2^-21
                                    (float)a0i * 0.0078125f);            // 2^-7
                    float bg = (r >> 1) ? bg1 : bg0;
                    float i2 = fmaf(f, gain, bg);
                    int idx = (nh * 2 + n2) * 4 + r;
                    v2[idx] += (i2 - v2[idx]) * invtau;
                    if (v2[idx] >= th2) { cnt[idx] += 1.0f; v2[idx] = 0.0f; }
                }
        }
    }

    // ---- pool: sum counts per c2 ----
    float t0 = 0.0f, t1 = 0.0f;
#pragma unroll
    for (int nt = 0; nt < 4; nt++)
#pragma unroll
        for (int r = 0; r < 4; r++) {
            if (r >> 1) t1 += cnt[nt * 4 + r];
            else        t0 += cnt[nt * 4 + r];
        }
    t0 += __shfl_xor_sync(0xffffffffu, t0, 1);
    t0 += __shfl_xor_sync(0xffffffffu, t0, 2);
    t1 += __shfl_xor_sync(0xffffffffu, t1, 1);
    t1 += __shfl_xor_sync(0xffffffffu, t1, 2);
    if (tid4 == 0) {
        atomicAdd(&g_pool[b * NC2 + 16 * j + gid],     t0);   // integer-valued
        atomicAdd(&g_pool[b * NC2 + 16 * j + gid + 8], t1);
    }
}

// ---------------------------------------------------------------------------
// k_fc: pooled = counts / (T*L); logits = pooled @ fc_w.T + fc_b
// ---------------------------------------------------------------------------
__global__ void k_fc(const float* __restrict__ fw,
                     const float* __restrict__ fb,
                     float* __restrict__ out) {
    int tid = threadIdx.x;
    int b = tid >> 2;
    int n = tid & 3;
    const float sc = 1.0f / (float)(TT * LL);
    float s = fb[n];
#pragma unroll
    for (int c = 0; c < NC2; c++)
        s += (g_pool[b * NC2 + c] * sc) * fw[n * NC2 + c];
    out[b * NCLS + n] = s;
}

// ---------------------------------------------------------------------------
extern "C" void kernel_launch(void* const* d_in, const int* in_sizes, int n_in,
                              void* d_out, int out_size) {
    const float* x    = (const float*)d_in[0];
    const float* w1   = (const float*)d_in[1];
    const float* b1   = (const float*)d_in[2];
    const float* w2   = (const float*)d_in[3];
    const float* b2   = (const float*)d_in[4];
    const float* gain = (const float*)d_in[5];
    const float* th1  = (const float*)d_in[6];
    const float* th2  = (const float*)d_in[7];
    const float* fw   = (const float*)d_in[8];
    const float* fb   = (const float*)d_in[9];
    float* out = (float*)d_out;

    cudaFuncSetAttribute(k_snn, cudaFuncAttributeMaxDynamicSharedMemorySize,
                         SNN_SMEM);

    k_pre<<<36, 256>>>(w2);

    dim3 g1(LL / 32, BB);
    k_conv1<<<g1, 256>>>(x, w1, b1, gain, th1);

    k_snn<<<BB * NTILES, 512, SNN_SMEM>>>(b2, gain, th2);

    k_fc<<<1, 256>>>(fw, fb, out);
}

// round 9
// speedup vs baseline: 1.1105x; 1.1105x over previous
#include <cuda_runtime.h>
#include <cuda_bf16.h>
#include <cstdint>

#define BB   64
#define CIN  12
#define LL   4096
#define TT   20
#define NC1  64
#define NC2  64
#define NCLS 4
#define NLT  128
#define NTILES 32
#define NBP  132
#define NCH  4                    // timesteps per chunk
#define NCHUNK 5

typedef unsigned long long ull;
typedef unsigned int u32;

__device__ float g_pool[BB * NC2];
// bf16 A fragments (K=64 per-tap, hi/lo planes), exact mma lane order
__device__ u32 g_Ah[6144];
__device__ u32 g_Al[6144];

// ---------------- packed f32x2 helpers --------------------------------------
#define FMA_F32X2(d, a, b, c) \
    asm("fma.rn.f32x2 %0, %1, %2, %3;" : "=l"(d) : "l"(a), "l"(b), "l"(c))
#define PACK_F32X2(out, lo, hi) \
    asm("mov.b64 %0, {%1, %2};" : "=l"(out) : "f"(lo), "f"(hi))
#define UNPACK_F32X2(lo, hi, in) \
    asm("mov.b64 {%0, %1}, %2;" : "=f"(lo), "=f"(hi) : "l"(in))

// mma.sync m16n8k16 bf16, fp32 accumulate (baseline PTX, sm_80+)
#define MMA16816(d, a, b) \
    asm volatile("mma.sync.aligned.m16n8k16.row.col.f32.bf16.bf16.f32 " \
        "{%0,%1,%2,%3}, {%4,%5,%6,%7}, {%8,%9}, {%0,%1,%2,%3};" \
        : "+f"((d)[0]), "+f"((d)[1]), "+f"((d)[2]), "+f"((d)[3]) \
        : "r"((a).x), "r"((a).y), "r"((a).z), "r"((a).w), \
          "r"((b).x), "r"((b).y))

#define BAR_SYNC(id, cnt) \
    asm volatile("bar.sync %0, %1;" :: "r"(id), "r"(cnt) : "memory")

// channel permutation matching the R6 multiply-spread decode:
// bits (i, i+16) of half-word mask -> k-positions (2a, 2a+1), a = h*16+i
__device__ __forceinline__ int chan_for_k(int kappa) {
    int a  = kappa >> 1;
    int hh = a >> 4;
    int ii = a & 15;
    return hh * 32 + ii + ((kappa & 1) << 4);
}

// ---------------------------------------------------------------------------
// k_pre: zero pool + build per-tap bf16 A fragments (hi/lo split, ~exact)
// ---------------------------------------------------------------------------
__global__ void k_pre(const float* __restrict__ w2) {
    int i = blockIdx.x * blockDim.x + threadIdx.x;
    if (i < BB * NC2) g_pool[i] = 0.0f;
    if (i < 6144) {
        int r    = i & 3;
        int idx4 = i >> 2;
        int lane = idx4 & 31;
        int rest = idx4 >> 5;        // (j*3+kk)*4 + s
        int s    = rest & 3;
        int kkj  = rest >> 2;
        int kk   = kkj % 3;
        int j    = kkj / 3;
        int gid  = lane >> 2;
        int t4   = lane & 3;
        int m    = 16 * j + gid + 8 * (r & 1);
        u32 hi = 0, lo = 0;
#pragma unroll
        for (int e = 0; e < 2; e++) {
            int kappa = 16 * s + 2 * t4 + 8 * (r >> 1) + e;
            int c1    = chan_for_k(kappa);
            float wv  = w2[m * (NC1 * 3) + c1 * 3 + kk];
            __nv_bfloat16 bh = __float2bfloat16(wv);
            __nv_bfloat16 bl = __float2bfloat16(wv - __bfloat162float(bh));
            hi |= (u32)__bfloat16_as_ushort(bh) << (16 * e);
            lo |= (u32)__bfloat16_as_ushort(bl) << (16 * e);
        }
        g_Ah[i] = hi;
        g_Al[i] = lo;
    }
}

// ---------------------------------------------------------------------------
// k_fused: warp-specialized conv1 (FMA pipe) + conv2 HMMA (tensor pipe) + LIF.
// 640 threads: warps 0-15 = MMA group (R6 k_snn), warps 16-19 = conv1 group.
// Per 4-t chunk: conv1 warps stage x and produce spike bits for chunk c+1
// while MMA warps run decode/HMMA/LIF for chunk c — pipes overlap.
// smem (u32): Ash[0,6144) Asl[6144,12288) B[12288,20736) x[20736,27072)
//             bits[27072,29152)  => 116608 bytes
// ---------------------------------------------------------------------------
#define OFF_ASL  6144
#define OFF_B    12288
#define OFF_XS   20736
#define OFF_BITS 27072
#define FUSED_SMEM (29152 * 4)

__global__ __launch_bounds__(640, 1) void k_fused(
        const float* __restrict__ x,
        const float* __restrict__ w1,
        const float* __restrict__ b1,
        const float* __restrict__ b2,
        const float* __restrict__ pgain,
        const float* __restrict__ pth1,
        const float* __restrict__ pth2) {
    extern __shared__ __align__(16) u32 smw[];
    u32*   Ash  = smw;
    u32*   Asl  = smw + OFF_ASL;
    u32*   Bs   = smw + OFF_B;
    float* xs   = (float*)(smw + OFF_XS);     // [12][132][4]
    u32*   bits = smw + OFF_BITS;             // 2 x [4 t][2 half][130 l]

    const int tid  = threadIdx.x;
    const int b    = blockIdx.x >> 5;
    const int l0   = (blockIdx.x & 31) * NLT;
    const int w    = tid >> 5;
    const int lane = tid & 31;

    const float gain = *pgain;

    // ======================= conv1 group state ==============================
    ull   wrp[CIN * 3];
    float c1bias = 0.0f, th1 = 0.0f;
    int   chalf = 0, ctp = 0;

    // =========================== prologue ===================================
    if (w < 16) {
        // stage A fragments (L2-hot, identical across CTAs)
        for (int i = tid; i < 1536; i += 512) {
            ((uint4*)Ash)[i] = ((const uint4*)g_Ah)[i];
            ((uint4*)Asl)[i] = ((const uint4*)g_Al)[i];
        }
    } else {
        const int wi = w - 16;
        chalf = wi & 1;
        ctp   = wi >> 1;
        const int c1 = chalf * 32 + lane;
#pragma unroll
        for (int c = 0; c < CIN; c++)
#pragma unroll
            for (int k = 0; k < 3; k++) {
                float wv = w1[c1 * (CIN * 3) + c * 3 + k];
                PACK_F32X2(wrp[c * 3 + k], wv, wv);
            }
        c1bias = b1[c1];
        th1    = *pth1;

        // stage x for chunk 0 (t0 = 0), 12x132 float4 rows over 128 threads
        const int ctid = tid - 512;
        for (int i = ctid; i < CIN * 132; i += 128) {
            int cc = i / 132, lxs = i % 132;
            int gl = l0 - 2 + lxs;
            float4 v = make_float4(0.f, 0.f, 0.f, 0.f);
            if (gl >= 0 && gl < LL)
                v = *(const float4*)&x[((size_t)(b * CIN + cc) * LL + gl) * TT];
            *(float4*)&xs[(cc * 132 + lxs) * 4] = v;
        }
        BAR_SYNC(2, 128);

        // compute spike bits for chunk 0 into bits buffer 0
        for (int lx = 0; lx < 130; lx++) {
            int gl = l0 - 1 + lx;
            if (gl >= 0 && gl < LL) {
                ull a01 = 0ull;
#pragma unroll
                for (int c = 0; c < CIN; c++)
#pragma unroll
                    for (int k = 0; k < 3; k++) {
                        ull xq = *(const ull*)&xs[(c * 132 + lx + k) * 4 + ctp * 2];
                        FMA_F32X2(a01, xq, wrp[c * 3 + k], a01);
                    }
                float a0, a1;
                UNPACK_F32X2(a0, a1, a01);
                u32 m0 = __ballot_sync(0xffffffffu, (a0 + c1bias) * gain >= th1);
                u32 m1 = __ballot_sync(0xffffffffu, (a1 + c1bias) * gain >= th1);
                if (lane == 0) {
                    bits[((ctp * 2 + 0) * 2 + chalf) * 130 + lx] = m0;
                    bits[((ctp * 2 + 1) * 2 + chalf) * 130 + lx] = m1;
                }
            } else if (lane == 0) {
                bits[((ctp * 2 + 0) * 2 + chalf) * 130 + lx] = 0;
                bits[((ctp * 2 + 1) * 2 + chalf) * 130 + lx] = 0;
            }
        }
    }

    // ======================= MMA group state ================================
    const int j    = w & 3;
    const int q    = w >> 2;
    const int gid  = lane >> 2;
    const int tid4 = lane & 3;
    const float th2    = *pth2;
    const float invtau = 1.0f / 0.9f;
    const float bia0   = b2[(16 * (w & 3) + gid) & 63];
    const float bia1   = b2[(16 * (w & 3) + gid + 8) & 63];
    const bool  dact   = tid < 260;
    const int   dh     = (tid >= 130) ? 1 : 0;
    const int   dn     = tid - 130 * dh;

    float v2[16], cnt[16];
#pragma unroll
    for (int i = 0; i < 16; i++) { v2[i] = 0.0f; cnt[i] = 0.0f; }

    __syncthreads();

    // =========================== main loop ==================================
    for (int c = 0; c < NCHUNK; c++) {
        if (w < 16) {
            // -------- MMA group: process chunk c --------
            const u32* bb = bits + (c & 1) * 1040;
#pragma unroll 1
            for (int k = 0; k < NCH; k++) {
                const int t = c * NCH + k;
                const int p = t & 1;
                u32* Bp = Bs + p * 4224;

                // decode spike bits -> bf16 B tile (fragment order)
                if (dact) {
                    u32 m = bb[(k * 2 + dh) * 130 + dn];
                    u32 o[16];
#pragma unroll
                    for (int i = 0; i < 16; i++)
                        o[i] = ((m >> i) & 0x00010001u) * 0x3F80u;
                    u32* r0 = Bp + ((2 * dh)     * NBP + dn) * 8;
                    u32* r1 = Bp + ((2 * dh + 1) * NBP + dn) * 8;
                    ((uint4*)r0)[0] = make_uint4(o[0],  o[4],  o[1],  o[5]);
                    ((uint4*)r0)[1] = make_uint4(o[2],  o[6],  o[3],  o[7]);
                    ((uint4*)r1)[0] = make_uint4(o[8],  o[12], o[9],  o[13]);
                    ((uint4*)r1)[1] = make_uint4(o[10], o[14], o[11], o[15]);
                }
                BAR_SYNC(1, 512);

                // mma: 4 ksteps x 3 taps, hi+lo chained, 4 n-tiles
                float acc[4][4];
#pragma unroll
                for (int nt = 0; nt < 4; nt++)
#pragma unroll
                    for (int r = 0; r < 4; r++) acc[nt][r] = 0.0f;

#pragma unroll
                for (int s = 0; s < 4; s++) {
#pragma unroll
                    for (int kk = 0; kk < 3; kk++) {
                        int abase = (((j * 3 + kk) * 4 + s) * 32 + lane) * 4;
                        uint4 ah = *(const uint4*)&Ash[abase];
                        uint4 al = *(const uint4*)&Asl[abase];
#pragma unroll
                        for (int nt = 0; nt < 4; nt++) {
                            int nrow = q * 32 + nt * 8 + gid + kk;
                            uint2 bbf = *(const uint2*)&Bp[(s * NBP + nrow) * 8 + tid4 * 2];
                            MMA16816(acc[nt], ah, bbf);
                            MMA16816(acc[nt], al, bbf);
                        }
                    }
                }

                // LIF epilogue in registers
#pragma unroll
                for (int nt = 0; nt < 4; nt++)
#pragma unroll
                    for (int r = 0; r < 4; r++) {
                        float bia = (r >> 1) ? bia1 : bia0;
                        float i2  = (acc[nt][r] + bia) * gain;
                        int idx = nt * 4 + r;
                        v2[idx] += (i2 - v2[idx]) * invtau;
                        if (v2[idx] >= th2) { cnt[idx] += 1.0f; v2[idx] = 0.0f; }
                    }
            }
        } else if (c + 1 < NCHUNK) {
            // -------- conv1 group: produce chunk c+1 --------
            const int cc = c + 1;
            const int t0 = cc * NCH;
            const int ctid = tid - 512;
            for (int i = ctid; i < CIN * 132; i += 128) {
                int ch = i / 132, lxs = i % 132;
                int gl = l0 - 2 + lxs;
                float4 v = make_float4(0.f, 0.f, 0.f, 0.f);
                if (gl >= 0 && gl < LL)
                    v = *(const float4*)&x[((size_t)(b * CIN + ch) * LL + gl) * TT + t0];
                *(float4*)&xs[(ch * 132 + lxs) * 4] = v;
            }
            BAR_SYNC(2, 128);

            u32* bo = bits + (cc & 1) * 1040;
            for (int lx = 0; lx < 130; lx++) {
                int gl = l0 - 1 + lx;
                if (gl >= 0 && gl < LL) {
                    ull a01 = 0ull;
#pragma unroll
                    for (int ch = 0; ch < CIN; ch++)
#pragma unroll
                        for (int k = 0; k < 3; k++) {
                            ull xq = *(const ull*)&xs[(ch * 132 + lx + k) * 4 + ctp * 2];
                            FMA_F32X2(a01, xq, wrp[ch * 3 + k], a01);
                        }
                    float a0, a1;
                    UNPACK_F32X2(a0, a1, a01);
                    u32 m0 = __ballot_sync(0xffffffffu, (a0 + c1bias) * gain >= th1);
                    u32 m1 = __ballot_sync(0xffffffffu, (a1 + c1bias) * gain >= th1);
                    if (lane == 0) {
                        bo[((ctp * 2 + 0) * 2 + chalf) * 130 + lx] = m0;
                        bo[((ctp * 2 + 1) * 2 + chalf) * 130 + lx] = m1;
                    }
                } else if (lane == 0) {
                    bo[((ctp * 2 + 0) * 2 + chalf) * 130 + lx] = 0;
                    bo[((ctp * 2 + 1) * 2 + chalf) * 130 + lx] = 0;
                }
            }
        }
        __syncthreads();
    }

    // ========================= pooling ======================================
    if (w < 16) {
        float t0s = 0.0f, t1s = 0.0f;
#pragma unroll
        for (int nt = 0; nt < 4; nt++)
#pragma unroll
            for (int r = 0; r < 4; r++) {
                if (r >> 1) t1s += cnt[nt * 4 + r];
                else        t0s += cnt[nt * 4 + r];
            }
        t0s += __shfl_xor_sync(0xffffffffu, t0s, 1);
        t0s += __shfl_xor_sync(0xffffffffu, t0s, 2);
        t1s += __shfl_xor_sync(0xffffffffu, t1s, 1);
        t1s += __shfl_xor_sync(0xffffffffu, t1s, 2);
        if (tid4 == 0) {
            atomicAdd(&g_pool[b * NC2 + 16 * j + gid],     t0s);  // integer-valued
            atomicAdd(&g_pool[b * NC2 + 16 * j + gid + 8], t1s);
        }
    }
}

// ---------------------------------------------------------------------------
// k_fc: pooled = counts / (T*L); logits = pooled @ fc_w.T + fc_b
// ---------------------------------------------------------------------------
__global__ void k_fc(const float* __restrict__ fw,
                     const float* __restrict__ fb,
                     float* __restrict__ out) {
    int tid = threadIdx.x;
    int b = tid >> 2;
    int n = tid & 3;
    const float sc = 1.0f / (float)(TT * LL);
    float s = fb[n];
#pragma unroll
    for (int c = 0; c < NC2; c++)
        s += (g_pool[b * NC2 + c] * sc) * fw[n * NC2 + c];
    out[b * NCLS + n] = s;
}

// ---------------------------------------------------------------------------
extern "C" void kernel_launch(void* const* d_in, const int* in_sizes, int n_in,
                              void* d_out, int out_size) {
    const float* x    = (const float*)d_in[0];
    const float* w1   = (const float*)d_in[1];
    const float* b1   = (const float*)d_in[2];
    const float* w2   = (const float*)d_in[3];
    const float* b2   = (const float*)d_in[4];
    const float* gain = (const float*)d_in[5];
    const float* th1  = (const float*)d_in[6];
    const float* th2  = (const float*)d_in[7];
    const float* fw   = (const float*)d_in[8];
    const float* fb   = (const float*)d_in[9];
    float* out = (float*)d_out;

    cudaFuncSetAttribute(k_fused, cudaFuncAttributeMaxDynamicSharedMemorySize,
                         FUSED_SMEM);

    k_pre<<<24, 256>>>(w2);

    k_fused<<<BB * NTILES, 640, FUSED_SMEM>>>(x, w1, b1, b2, gain, th1, th2);

    k_fc<<<1, 256>>>(fw, fb, out);
}

// round 10
// speedup vs baseline: 2.4251x; 2.1838x over previous
#include <cuda_runtime.h>
#include <cuda_bf16.h>
#include <cstdint>

#define BB   64
#define CIN  12
#define LL   4096
#define TT   20
#define NC1  64
#define NC2  64
#define NCLS 4
#define NLT  128                 // l positions per tile
#define NTILES (LL / NLT)        // 32
#define NBP  132                 // padded B rows (130 used)

typedef unsigned long long ull;
typedef unsigned int u32;

// spike bits: 2x u32 per (b,t,l)
__device__ u32 g_s1[BB * TT * LL * 2];
// per (b,c2) spike counts
__device__ float g_pool[BB * NC2];
// bf16 A fragments (K=64 per-tap, hi/lo planes), exact mma lane order
__device__ u32 g_Ah[6144];
__device__ u32 g_Al[6144];

// ---------------- packed f32x2 helpers (conv1) ------------------------------
#define FMA_F32X2(d, a, b, c) \
    asm("fma.rn.f32x2 %0, %1, %2, %3;" : "=l"(d) : "l"(a), "l"(b), "l"(c))
#define PACK_F32X2(out, lo, hi) \
    asm("mov.b64 %0, {%1, %2};" : "=l"(out) : "f"(lo), "f"(hi))
#define UNPACK_F32X2(lo, hi, in) \
    asm("mov.b64 {%0, %1}, %2;" : "=f"(lo), "=f"(hi) : "l"(in))

// mma.sync m16n8k16 bf16, fp32 accumulate (baseline PTX, sm_80+)
#define MMA16816(d, a, b) \
    asm volatile("mma.sync.aligned.m16n8k16.row.col.f32.bf16.bf16.f32 " \
        "{%0,%1,%2,%3}, {%4,%5,%6,%7}, {%8,%9}, {%0,%1,%2,%3};" \
        : "+f"((d)[0]), "+f"((d)[1]), "+f"((d)[2]), "+f"((d)[3]) \
        : "r"((a).x), "r"((a).y), "r"((a).z), "r"((a).w), \
          "r"((b).x), "r"((b).y))

// channel permutation matching the multiply-spread decode:
// bits (i, i+16) of half-word mask -> k-positions (2a, 2a+1), a = h*16+i
__device__ __forceinline__ int chan_for_k(int kappa) {
    int a  = kappa >> 1;
    int hh = a >> 4;
    int ii = a & 15;
    return hh * 32 + ii + ((kappa & 1) << 4);
}

// ---------------------------------------------------------------------------
// k_pre: zero pool + build per-tap bf16 A fragments (hi/lo split, exact)
// ---------------------------------------------------------------------------
__global__ void k_pre(const float* __restrict__ w2) {
    int i = blockIdx.x * blockDim.x + threadIdx.x;
    if (i < BB * NC2) g_pool[i] = 0.0f;
    if (i < 6144) {
        int r    = i & 3;
        int idx4 = i >> 2;
        int lane = idx4 & 31;
        int rest = idx4 >> 5;        // (j*3+kk)*4 + s
        int s    = rest & 3;
        int kkj  = rest >> 2;
        int kk   = kkj % 3;
        int j    = kkj / 3;
        int gid  = lane >> 2;
        int t4   = lane & 3;
        int m    = 16 * j + gid + 8 * (r & 1);
        u32 hi = 0, lo = 0;
#pragma unroll
        for (int e = 0; e < 2; e++) {
            int kappa = 16 * s + 2 * t4 + 8 * (r >> 1) + e;
            int c1    = chan_for_k(kappa);
            float wv  = w2[m * (NC1 * 3) + c1 * 3 + kk];
            __nv_bfloat16 bh = __float2bfloat16(wv);
            __nv_bfloat16 bl = __float2bfloat16(wv - __bfloat162float(bh));
            hi |= (u32)__bfloat16_as_ushort(bh) << (16 * e);
            lo |= (u32)__bfloat16_as_ushort(bl) << (16 * e);
        }
        g_Ah[i] = hi;
        g_Al[i] = lo;
    }
}

// ---------------------------------------------------------------------------
// k_conv1: conv1 + threshold -> bit-packed spikes (TAU1=1 => stateless).
// (unchanged from R6: packed f32x2 over contiguous t axis)
// ---------------------------------------------------------------------------
__global__ __launch_bounds__(256) void k_conv1(
        const float* __restrict__ x,
        const float* __restrict__ w1,
        const float* __restrict__ b1,
        const float* __restrict__ pgain,
        const float* __restrict__ pth1) {
    __shared__ __align__(16) float s_x[CIN][34][TT];

    const int l0  = blockIdx.x * 32;
    const int b   = blockIdx.y;
    const int tid = threadIdx.x;

    for (int i = tid; i < CIN * 34 * TT; i += 256) {
        int c   = i / (34 * TT);
        int rem = i % (34 * TT);
        int lx  = rem / TT;
        int t   = rem % TT;
        int gl  = l0 - 1 + lx;
        float v = 0.0f;
        if (gl >= 0 && gl < LL)
            v = x[((size_t)(b * CIN + c) * LL + gl) * TT + t];
        s_x[c][lx][t] = v;
    }

    const int w    = tid >> 5;
    const int lane = tid & 31;
    const int half = w & 1;
    const int pair = w >> 1;
    const int c1   = half * 32 + lane;

    ull wrp[CIN][3];
#pragma unroll
    for (int c = 0; c < CIN; c++)
#pragma unroll
        for (int k = 0; k < 3; k++) {
            float wv = w1[c1 * (CIN * 3) + c * 3 + k];
            PACK_F32X2(wrp[c][k], wv, wv);
        }
    const float bias = b1[c1];
    const float gain = *pgain;
    const float th1  = *pth1;

    __syncthreads();

    for (int task = pair; task < 160; task += 4) {
        int ll = task & 31;
        int tg = task >> 5;
        int t0 = tg * 4;
        ull a01 = 0ull, a23 = 0ull;
#pragma unroll
        for (int c = 0; c < CIN; c++) {
#pragma unroll
            for (int k = 0; k < 3; k++) {
                ulonglong2 xq = *(const ulonglong2*)&s_x[c][ll + k][t0];
                FMA_F32X2(a01, xq.x, wrp[c][k], a01);
                FMA_F32X2(a23, xq.y, wrp[c][k], a23);
            }
        }
        float a[4];
        UNPACK_F32X2(a[0], a[1], a01);
        UNPACK_F32X2(a[2], a[3], a23);
        int gl = l0 + ll;
#pragma unroll
        for (int j = 0; j < 4; j++) {
            float i1 = (a[j] + bias) * gain;
            unsigned m = __ballot_sync(0xffffffffu, i1 >= th1);
            if (lane == 0)
                g_s1[((size_t)(b * TT + (t0 + j)) * LL + gl) * 2 + half] = m;
        }
    }
}

// ---------------------------------------------------------------------------
// k_snn: conv2 via mma.sync, 2-timestep batched (A fragments loaded once per
// pair -> A smem traffic and barriers halved vs R6).
// CTA = (b, 128-l tile), 512 threads = 16 warps; warp = m-tile j x n-quarter q.
// Per t-pair: decode both t into pair-buffer (double-buffered); one barrier;
// per (s,kk): 2 LDS.128 A, then 4 nt x (2 LDS.64 B, 4 HMMA); LIF in registers.
// smem u32: Ash[0,6144) Asl[6144,12288) B[12288, 12288+2*8448)
// ---------------------------------------------------------------------------
#define SNN_SMEM ((12288 + 2 * 8448) * 4)     // 116736 bytes

__global__ __launch_bounds__(512, 1) void k_snn(
        const float* __restrict__ b2,
        const float* __restrict__ pgain,
        const float* __restrict__ pth2) {
    extern __shared__ __align__(16) u32 smw[];
    u32* Ash = smw;
    u32* Asl = smw + 6144;
    u32* Bs  = smw + 12288;

    const int tid = threadIdx.x;
    const int b   = blockIdx.x >> 5;
    const int l0  = (blockIdx.x & 31) * NLT;

    // stage A fragments (L2-hot, identical for every CTA)
    for (int i = tid; i < 1536; i += 512) {
        ((uint4*)Ash)[i] = ((const uint4*)g_Ah)[i];
        ((uint4*)Asl)[i] = ((const uint4*)g_Al)[i];
    }

    const int w    = tid >> 5;
    const int lane = tid & 31;
    const int j    = w & 3;       // m-tile (16 c2 rows)
    const int q    = w >> 2;      // n-quarter (32 l)
    const int gid  = lane >> 2;
    const int tid4 = lane & 3;

    const float gain   = *pgain;
    const float th2    = *pth2;
    const float invtau = 1.0f / 0.9f;
    const float bia0   = b2[16 * j + gid];
    const float bia1   = b2[16 * j + gid + 8];

    // decode task assignment (260 tasks over 512 threads)
    const bool dact = tid < 260;
    int dh = 0, dn = 0;
    bool inrange = false;
    size_t gstep = 0, gaddr = 0;
    if (dact) {
        dh = (tid >= 130) ? 1 : 0;
        dn = tid - 130 * dh;
        int gl  = l0 - 1 + dn;
        inrange = (gl >= 0 && gl < LL);
        if (inrange) {
            gaddr = ((size_t)(b * TT) * LL + gl) * 2 + dh;
            gstep = (size_t)LL * 2;
        }
    }

    float v2[16], cnt[16];
#pragma unroll
    for (int i = 0; i < 16; i++) { v2[i] = 0.0f; cnt[i] = 0.0f; }

    u32 m0n = 0, m1n = 0;
    if (dact && inrange) {
        m0n = g_s1[gaddr];
        m1n = g_s1[gaddr + gstep];
    }

    __syncthreads();

#pragma unroll 1
    for (int tp = 0; tp < TT / 2; tp++) {
        const int p = tp & 1;
        u32* Bq0 = Bs + p * 8448;
        u32* Bq1 = Bq0 + 4224;

        // ---- decode both timesteps of the pair; prefetch next pair ----
        u32 mc0 = m0n, mc1 = m1n;
        if (dact && inrange && tp + 1 < TT / 2) {
            m0n = g_s1[gaddr + (size_t)(2 * tp + 2) * gstep];
            m1n = g_s1[gaddr + (size_t)(2 * tp + 3) * gstep];
        }
        if (dact) {
            u32 o[16];
#pragma unroll
            for (int i = 0; i < 16; i++)
                o[i] = ((mc0 >> i) & 0x00010001u) * 0x3F80u;
            u32* r0 = Bq0 + ((2 * dh)     * NBP + dn) * 8;
            u32* r1 = Bq0 + ((2 * dh + 1) * NBP + dn) * 8;
            ((uint4*)r0)[0] = make_uint4(o[0],  o[4],  o[1],  o[5]);
            ((uint4*)r0)[1] = make_uint4(o[2],  o[6],  o[3],  o[7]);
            ((uint4*)r1)[0] = make_uint4(o[8],  o[12], o[9],  o[13]);
            ((uint4*)r1)[1] = make_uint4(o[10], o[14], o[11], o[15]);
#pragma unroll
            for (int i = 0; i < 16; i++)
                o[i] = ((mc1 >> i) & 0x00010001u) * 0x3F80u;
            r0 = Bq1 + ((2 * dh)     * NBP + dn) * 8;
            r1 = Bq1 + ((2 * dh + 1) * NBP + dn) * 8;
            ((uint4*)r0)[0] = make_uint4(o[0],  o[4],  o[1],  o[5]);
            ((uint4*)r0)[1] = make_uint4(o[2],  o[6],  o[3],  o[7]);
            ((uint4*)r1)[0] = make_uint4(o[8],  o[12], o[9],  o[13]);
            ((uint4*)r1)[1] = make_uint4(o[10], o[14], o[11], o[15]);
        }
        __syncthreads();

        // ---- mma: 4 ksteps x 3 taps; each A load feeds both timesteps ----
        float acc0[4][4], acc1[4][4];
#pragma unroll
        for (int nt = 0; nt < 4; nt++)
#pragma unroll
            for (int r = 0; r < 4; r++) { acc0[nt][r] = 0.0f; acc1[nt][r] = 0.0f; }

#pragma unroll
        for (int s = 0; s < 4; s++) {
#pragma unroll
            for (int kk = 0; kk < 3; kk++) {
                int abase = (((j * 3 + kk) * 4 + s) * 32 + lane) * 4;
                uint4 ah = *(const uint4*)&Ash[abase];
                uint4 al = *(const uint4*)&Asl[abase];
#pragma unroll
                for (int nt = 0; nt < 4; nt++) {
                    int boff = (s * NBP + q * 32 + nt * 8 + gid + kk) * 8 + tid4 * 2;
                    uint2 bb0 = *(const uint2*)&Bq0[boff];
                    uint2 bb1 = *(const uint2*)&Bq1[boff];
                    MMA16816(acc0[nt], ah, bb0);
                    MMA16816(acc0[nt], al, bb0);
                    MMA16816(acc1[nt], ah, bb1);
                    MMA16816(acc1[nt], al, bb1);
                }
            }
        }

        // ---- LIF epilogue (t then t+1), all in registers ----
#pragma unroll
        for (int nt = 0; nt < 4; nt++)
#pragma unroll
            for (int r = 0; r < 4; r++) {
                float bia = (r >> 1) ? bia1 : bia0;
                int idx = nt * 4 + r;
                float i2 = (acc0[nt][r] + bia) * gain;
                v2[idx] += (i2 - v2[idx]) * invtau;
                if (v2[idx] >= th2) { cnt[idx] += 1.0f; v2[idx] = 0.0f; }
                i2 = (acc1[nt][r] + bia) * gain;
                v2[idx] += (i2 - v2[idx]) * invtau;
                if (v2[idx] >= th2) { cnt[idx] += 1.0f; v2[idx] = 0.0f; }
            }
    }

    // ---- pool: sum counts per c2 ----
    float t0 = 0.0f, t1 = 0.0f;
#pragma unroll
    for (int nt = 0; nt < 4; nt++)
#pragma unroll
        for (int r = 0; r < 4; r++) {
            if (r >> 1) t1 += cnt[nt * 4 + r];
            else        t0 += cnt[nt * 4 + r];
        }
    t0 += __shfl_xor_sync(0xffffffffu, t0, 1);
    t0 += __shfl_xor_sync(0xffffffffu, t0, 2);
    t1 += __shfl_xor_sync(0xffffffffu, t1, 1);
    t1 += __shfl_xor_sync(0xffffffffu, t1, 2);
    if (tid4 == 0) {
        atomicAdd(&g_pool[b * NC2 + 16 * j + gid],     t0);   // integer-valued
        atomicAdd(&g_pool[b * NC2 + 16 * j + gid + 8], t1);
    }
}

// ---------------------------------------------------------------------------
// k_fc: pooled = counts / (T*L); logits = pooled @ fc_w.T + fc_b
// ---------------------------------------------------------------------------
__global__ void k_fc(const float* __restrict__ fw,
                     const float* __restrict__ fb,
                     float* __restrict__ out) {
    int tid = threadIdx.x;
    int b = tid >> 2;
    int n = tid & 3;
    const float sc = 1.0f / (float)(TT * LL);
    float s = fb[n];
#pragma unroll
    for (int c = 0; c < NC2; c++)
        s += (g_pool[b * NC2 + c] * sc) * fw[n * NC2 + c];
    out[b * NCLS + n] = s;
}

// ---------------------------------------------------------------------------
extern "C" void kernel_launch(void* const* d_in, const int* in_sizes, int n_in,
                              void* d_out, int out_size) {
    const float* x    = (const float*)d_in[0];
    const float* w1   = (const float*)d_in[1];
    const float* b1   = (const float*)d_in[2];
    const float* w2   = (const float*)d_in[3];
    const float* b2   = (const float*)d_in[4];
    const float* gain = (const float*)d_in[5];
    const float* th1  = (const float*)d_in[6];
    const float* th2  = (const float*)d_in[7];
    const float* fw   = (const float*)d_in[8];
    const float* fb   = (const float*)d_in[9];
    float* out = (float*)d_out;

    cudaFuncSetAttribute(k_snn, cudaFuncAttributeMaxDynamicSharedMemorySize,
                         SNN_SMEM);

    k_pre<<<24, 256>>>(w2);

    dim3 g1(LL / 32, BB);
    k_conv1<<<g1, 256>>>(x, w1, b1, gain, th1);

    k_snn<<<BB * NTILES, 512, SNN_SMEM>>>(b2, gain, th2);

    k_fc<<<1, 256>>>(fw, fb, out);
}